// round 7
// baseline (speedup 1.0000x reference)
#include <cuda_runtime.h>
#include <cstdint>
#include <math.h>

// ----------------------------------------------------------------------------
// DLRM forward: bottom MLP (13->512->256->64, ReLU) ; 26-table embedding bag
// (sum-pool, L=10, D=64) ; dot interaction (27x27 lower tri, 351 pairs) ;
// top MLP (415->512->256->1, ReLU/ReLU/Sigmoid).
//
// GEMMs use m16n8k8 TF32 tensor-core MMA with a 2-term (hi/lo) split per
// operand ("3xTF32"): products hi*hi + hi*lo + lo*hi give ~fp32 accuracy.
// ----------------------------------------------------------------------------

#define BB      8192        // batch
#define NTAB    26
#define LBAG    10
#define VROWS   200000
#define DD      64
#define TROW    1728        // 27*64 floats per batch row of T
#define RLD     416         // padded row stride of R (415 used)

// ---------------- scratch (device globals: no allocs allowed) ----------------
__device__ __align__(16) float g_h1[BB * 512];   // bot1 out / top1 out (z1)
__device__ __align__(16) float g_h2[BB * 256];   // bot2 out / top2 out (z2)
__device__ __align__(16) float g_T [BB * TROW];  // [B][27][64]: row0 = h, rows 1..26 = pooled
__device__ __align__(16) float g_R [BB * RLD];   // [B][416]: cols 0..63 = h, 64..414 = tril dots
__device__ int g_idx64;                           // 1 if lS_i is int64, 0 if int32

// ---------------- helpers ----------------
__device__ __forceinline__ uint32_t f2tf32(float x) {
    uint32_t r;
    asm("cvt.rna.tf32.f32 %0, %1;" : "=r"(r) : "f"(x));
    return r;
}

__device__ __forceinline__ void mma_tf32(float* d, const uint32_t* a, const uint32_t* b) {
    asm volatile(
        "mma.sync.aligned.m16n8k8.row.col.f32.tf32.tf32.f32 "
        "{%0,%1,%2,%3}, {%4,%5,%6,%7}, {%8,%9}, {%0,%1,%2,%3};\n"
        : "+f"(d[0]), "+f"(d[1]), "+f"(d[2]), "+f"(d[3])
        : "r"(a[0]), "r"(a[1]), "r"(a[2]), "r"(a[3]), "r"(b[0]), "r"(b[1]));
}

// ---------------- index-width autodetect ----------------
// If lS_i is int64 (values < 2^31, non-negative), every odd 32-bit word is 0.
// For int32 data, P(128 consecutive sampled indices all == 0) ~ (1/200000)^128.
__global__ void detect_idx_kernel(const unsigned int* __restrict__ p) {
    if (threadIdx.x == 0 && blockIdx.x == 0) {
        int f = 1;
        for (int i = 0; i < 128; i++) {
            if (p[2 * i + 1] != 0u) { f = 0; break; }
        }
        g_idx64 = f;
    }
}

// ---------------- GEMM: C = relu(A[8192,K] @ W[M,K]^T + bias) ----------------
// Block tile: 128 rows x 64 cols, BK=16. 256 threads = 8 warps (4 m x 2 n),
// warp tile 32x32 = (2 m16) x (4 n8). 3xTF32 split for fp32-class accuracy.
__global__ __launch_bounds__(256)
void gemm3tf32_relu(const float* __restrict__ A, int lda,
                    const float* __restrict__ W, int K,
                    const float* __restrict__ bias,
                    float* __restrict__ C, int ldc)
{
    __shared__ uint32_t Ah[128][17];
    __shared__ uint32_t Al[128][17];
    __shared__ uint32_t Wh[64][17];
    __shared__ uint32_t Wl[64][17];

    const int tid  = threadIdx.x;
    const int kld  = tid & 15;        // k slot this thread loads
    const int mth  = tid >> 4;        // 0..15: base m/n slot this thread loads
    const int warp = tid >> 5;
    const int lane = tid & 31;
    const int wm   = warp & 3;        // 0..3
    const int wn   = warp >> 2;       // 0..1
    const int gid  = lane >> 2;       // 0..7
    const int tig  = lane & 3;        // 0..3

    const long long rowBase = (long long)blockIdx.y * 128;
    const int colBase = blockIdx.x * 64;

    float acc[2][4][4];
    #pragma unroll
    for (int mt = 0; mt < 2; mt++)
        #pragma unroll
        for (int nt = 0; nt < 4; nt++)
            #pragma unroll
            for (int q = 0; q < 4; q++) acc[mt][nt][q] = 0.0f;

    for (int k0 = 0; k0 < K; k0 += 16) {
        const int gk = k0 + kld;
        const bool kin = (gk < K);
        // load + split A tile (128 x 16)
        #pragma unroll
        for (int i = 0; i < 8; i++) {
            const int m = mth + 16 * i;
            float v = 0.0f;
            if (kin) v = A[(rowBase + m) * (long long)lda + gk];
            const uint32_t hi = f2tf32(v);
            const float lo = v - __uint_as_float(hi);
            Ah[m][kld] = hi;
            Al[m][kld] = f2tf32(lo);
        }
        // load + split W tile (64 x 16)
        #pragma unroll
        for (int i = 0; i < 4; i++) {
            const int n = mth + 16 * i;
            float v = 0.0f;
            if (kin) v = W[(size_t)(colBase + n) * (size_t)K + gk];
            const uint32_t hi = f2tf32(v);
            const float lo = v - __uint_as_float(hi);
            Wh[n][kld] = hi;
            Wl[n][kld] = f2tf32(lo);
        }
        __syncthreads();

        #pragma unroll
        for (int kk = 0; kk < 2; kk++) {
            const int ks = kk * 8;
            uint32_t a_hi[2][4], a_lo[2][4];
            #pragma unroll
            for (int mt = 0; mt < 2; mt++) {
                const int r = wm * 32 + mt * 16 + gid;
                a_hi[mt][0] = Ah[r    ][ks + tig];
                a_hi[mt][1] = Ah[r + 8][ks + tig];
                a_hi[mt][2] = Ah[r    ][ks + tig + 4];
                a_hi[mt][3] = Ah[r + 8][ks + tig + 4];
                a_lo[mt][0] = Al[r    ][ks + tig];
                a_lo[mt][1] = Al[r + 8][ks + tig];
                a_lo[mt][2] = Al[r    ][ks + tig + 4];
                a_lo[mt][3] = Al[r + 8][ks + tig + 4];
            }
            uint32_t b_hi[4][2], b_lo[4][2];
            #pragma unroll
            for (int nt = 0; nt < 4; nt++) {
                const int n = wn * 32 + nt * 8 + gid;
                b_hi[nt][0] = Wh[n][ks + tig];
                b_hi[nt][1] = Wh[n][ks + tig + 4];
                b_lo[nt][0] = Wl[n][ks + tig];
                b_lo[nt][1] = Wl[n][ks + tig + 4];
            }
            #pragma unroll
            for (int mt = 0; mt < 2; mt++)
                #pragma unroll
                for (int nt = 0; nt < 4; nt++) {
                    mma_tf32(acc[mt][nt], a_hi[mt], b_hi[nt]);
                    mma_tf32(acc[mt][nt], a_hi[mt], b_lo[nt]);
                    mma_tf32(acc[mt][nt], a_lo[mt], b_hi[nt]);
                }
        }
        __syncthreads();
    }

    // epilogue: bias + relu, float2 stores
    #pragma unroll
    for (int mt = 0; mt < 2; mt++)
        #pragma unroll
        for (int nt = 0; nt < 4; nt++) {
            const long long row = rowBase + wm * 32 + mt * 16 + gid;
            const int col = colBase + wn * 32 + nt * 8 + 2 * tig;
            const float b0 = bias[col];
            const float b1 = bias[col + 1];
            float2 v01, v23;
            v01.x = fmaxf(acc[mt][nt][0] + b0, 0.0f);
            v01.y = fmaxf(acc[mt][nt][1] + b1, 0.0f);
            v23.x = fmaxf(acc[mt][nt][2] + b0, 0.0f);
            v23.y = fmaxf(acc[mt][nt][3] + b1, 0.0f);
            *reinterpret_cast<float2*>(&C[row * ldc + col])       = v01;
            *reinterpret_cast<float2*>(&C[(row + 8) * ldc + col]) = v23;
        }
}

// ---------------- embedding bag: sum-pool 10 rows of 64 floats --------------
// 256 threads = 16 bags x 16 float4-columns. Writes T[b][1+t][:].
__global__ void embed_kernel(const void* __restrict__ lSi, const float* __restrict__ emb)
{
    const int c   = threadIdx.x & 15;          // float4 column
    const int bag = threadIdx.x >> 4;          // 0..15
    const int t   = blockIdx.x >> 9;           // table (512 blocks per table)
    const int b   = ((blockIdx.x & 511) << 4) + bag;

    const float4* tab = reinterpret_cast<const float4*>(emb) + (size_t)t * (size_t)(VROWS * (DD / 4));
    const long long ibase = (long long)t * (BB * LBAG) + (long long)b * LBAG;

    int idx[LBAG];
    if (g_idx64) {
        const long long* I = reinterpret_cast<const long long*>(lSi);
        #pragma unroll
        for (int j = 0; j < LBAG; j++) idx[j] = (int)I[ibase + j];
    } else {
        const int* I = reinterpret_cast<const int*>(lSi);
        #pragma unroll
        for (int j = 0; j < LBAG; j++) idx[j] = I[ibase + j];
    }

    float4 acc = make_float4(0.f, 0.f, 0.f, 0.f);
    #pragma unroll
    for (int j = 0; j < LBAG; j++) {
        const float4 v = tab[(size_t)idx[j] * (DD / 4) + c];
        acc.x += v.x; acc.y += v.y; acc.z += v.z; acc.w += v.w;
    }
    reinterpret_cast<float4*>(g_T)[(size_t)b * (TROW / 4) + (1 + t) * (DD / 4) + c] = acc;
}

// ---------------- dot interaction: R[b] = [h(64), tril dots(351)] -----------
__global__ void interact_kernel()
{
    __shared__ __align__(16) float Ts[TROW];
    const int b = blockIdx.x;
    const float4* Tb = reinterpret_cast<const float4*>(g_T + (size_t)b * TROW);
    float4* Ts4 = reinterpret_cast<float4*>(Ts);
    for (int i = threadIdx.x; i < TROW / 4; i += 128) Ts4[i] = Tb[i];
    __syncthreads();

    float* Rb = g_R + (size_t)b * RLD;
    if (threadIdx.x < 64) Rb[threadIdx.x] = Ts[threadIdx.x];   // copy h

    for (int p = threadIdx.x; p < 351; p += 128) {
        // invert p -> (i, j): p = i*(i-1)/2 + j, j < i  (tril row-major order)
        int i = (int)((1.0f + sqrtf(1.0f + 8.0f * (float)p)) * 0.5f);
        while (i * (i - 1) / 2 > p) --i;
        while ((i + 1) * i / 2 <= p) ++i;
        const int j = p - i * (i - 1) / 2;

        const float4* ri = Ts4 + i * (DD / 4);
        const float4* rj = Ts4 + j * (DD / 4);
        float s = 0.0f;
        #pragma unroll
        for (int k = 0; k < DD / 4; k++) {
            const float4 u = ri[k];
            const float4 v = rj[k];
            s += u.x * v.x + u.y * v.y + u.z * v.z + u.w * v.w;
        }
        Rb[64 + p] = s;
    }
}

// ---------------- top layer 3: out[b] = sigmoid(dot(z2[b], w3) + b3) --------
__global__ void top3_kernel(const float* __restrict__ w3, const float* __restrict__ b3,
                            float* __restrict__ out)
{
    const int gwarp = (int)((blockIdx.x * blockDim.x + threadIdx.x) >> 5);  // batch row
    const int lane  = threadIdx.x & 31;
    const float4* z = reinterpret_cast<const float4*>(g_h2) + (size_t)gwarp * 64;
    const float4* w = reinterpret_cast<const float4*>(w3);

    const float4 z0 = z[lane],      w0 = w[lane];
    const float4 z1 = z[lane + 32], w1 = w[lane + 32];
    float s = z0.x * w0.x + z0.y * w0.y + z0.z * w0.z + z0.w * w0.w
            + z1.x * w1.x + z1.y * w1.y + z1.z * w1.z + z1.w * w1.w;
    #pragma unroll
    for (int o = 16; o > 0; o >>= 1) s += __shfl_xor_sync(0xffffffffu, s, o);
    if (lane == 0) out[gwarp] = 1.0f / (1.0f + expf(-(s + b3[0])));
}

// ---------------- host ----------------
static void run_gemm(const float* A, int lda, const float* W, int K,
                     const float* bias, float* C, int ldc, int M)
{
    dim3 grid(M / 64, BB / 128);
    gemm3tf32_relu<<<grid, 256>>>(A, lda, W, K, bias, C, ldc);
}

extern "C" void kernel_launch(void* const* d_in, const int* in_sizes, int n_in,
                              void* d_out, int out_size)
{
    // --- input-order autodetect: insertion order (x first) vs alphabetical ---
    int IX_X, IX_LSI, IX_EMB, IX_BW1, IX_BB1, IX_BW2, IX_BB2, IX_BW3, IX_BB3;
    int IX_TW1, IX_TB1, IX_TW2, IX_TB2, IX_TW3, IX_TB3;
    if (in_sizes[0] == BB * 13) {
        // setup_inputs() insertion order
        IX_X = 0; IX_LSI = 1; IX_EMB = 3;
        IX_BW1 = 4;  IX_BB1 = 5;  IX_BW2 = 6;  IX_BB2 = 7;  IX_BW3 = 8;  IX_BB3 = 9;
        IX_TW1 = 10; IX_TB1 = 11; IX_TW2 = 12; IX_TB2 = 13; IX_TW3 = 14; IX_TB3 = 15;
    } else {
        // alphabetical: bot_W1,bot_W2,bot_W3,bot_b1,bot_b2,bot_b3,emb_tables,
        //               lS_i,lS_o,top_W1,top_W2,top_W3,top_b1,top_b2,top_b3,x
        IX_BW1 = 0; IX_BW2 = 1; IX_BW3 = 2; IX_BB1 = 3; IX_BB2 = 4; IX_BB3 = 5;
        IX_EMB = 6; IX_LSI = 7;
        IX_TW1 = 9; IX_TW2 = 10; IX_TW3 = 11; IX_TB1 = 12; IX_TB2 = 13; IX_TB3 = 14;
        IX_X = 15;
    }

    const float* x    = (const float*)d_in[IX_X];
    const void*  lSi  = d_in[IX_LSI];
    const float* emb  = (const float*)d_in[IX_EMB];
    const float* bw1  = (const float*)d_in[IX_BW1];
    const float* bb1  = (const float*)d_in[IX_BB1];
    const float* bw2  = (const float*)d_in[IX_BW2];
    const float* bb2  = (const float*)d_in[IX_BB2];
    const float* bw3  = (const float*)d_in[IX_BW3];
    const float* bb3  = (const float*)d_in[IX_BB3];
    const float* tw1  = (const float*)d_in[IX_TW1];
    const float* tb1  = (const float*)d_in[IX_TB1];
    const float* tw2  = (const float*)d_in[IX_TW2];
    const float* tb2  = (const float*)d_in[IX_TB2];
    const float* tw3  = (const float*)d_in[IX_TW3];
    const float* tb3  = (const float*)d_in[IX_TB3];
    float* out = (float*)d_out;

    float *h1, *h2, *T, *R;
    cudaGetSymbolAddress((void**)&h1, g_h1);
    cudaGetSymbolAddress((void**)&h2, g_h2);
    cudaGetSymbolAddress((void**)&T,  g_T);
    cudaGetSymbolAddress((void**)&R,  g_R);

    // 0) detect index width (deterministic: depends only on input data)
    detect_idx_kernel<<<1, 32>>>((const unsigned int*)lSi);

    // 1) bottom MLP: 13 -> 512 -> 256 -> 64 (ReLU), last writes T[b][0][:]
    run_gemm(x,  13,  bw1, 13,  bb1, h1, 512, 512);
    run_gemm(h1, 512, bw2, 512, bb2, h2, 256, 256);
    run_gemm(h2, 256, bw3, 256, bb3, T,  TROW, 64);

    // 2) embedding bag sum-pool -> T[b][1+t][:]
    embed_kernel<<<NTAB * (BB / 16), 256>>>(lSi, emb);

    // 3) dot interaction -> R[b][0..414]
    interact_kernel<<<BB, 128>>>();

    // 4) top MLP: 415 -> 512 -> 256 (ReLU), reuse h1/h2 as z1/z2
    run_gemm(R,  RLD, tw1, 415, tb1, h1, 512, 512);
    run_gemm(h1, 512, tw2, 512, tb2, h2, 256, 256);

    // 5) final 256 -> 1 dot + sigmoid
    top3_kernel<<<BB / 8, 256>>>(tw3, tb3, out);
}